// round 2
// baseline (speedup 1.0000x reference)
#include <cuda_runtime.h>
#include <cuda_bf16.h>
#include <cstdint>

// Problem constants
#define NIMG   8
#define CDIM   256
#define HWDIM  9216
#define TT     32
#define VV     256
#define TV     8192      // TT*VV rows
#define TILE   128
#define NTILES 64        // TV / TILE
#define RS     264       // padded smem row stride in bf16 elements (256 + 8)

#define SMEM_BYTES (2 * TILE * RS * 2)   // A tile + B tile, bf16

// Persistent device scratch (no dynamic allocation allowed)
__device__ __nv_bfloat16 g_feats[(size_t)TV * CDIM];  // normalized features, bf16 row-major
__device__ float g_neg_sum[TV];
__device__ float g_row_loss[TV];
__device__ int   g_is64;                 // sample_inds stored as int64? (detected at runtime)

// ---------------------------------------------------------------------------
// Fast exp on the FMA pipe: exp(x) = 2^(x*log2e), floor range reduction,
// degree-6 poly for 2^r on [0,1), exponent assembled via integer bit trick.
// Valid for x in ~[-6, +0.1]; rel err ~2e-5.
// ---------------------------------------------------------------------------
__device__ __forceinline__ float fexp(float x) {
    float y  = x * 1.4426950408889634f;
    float fl = floorf(y);
    float r  = y - fl;
    float p  = 1.5403530393381609e-4f;
    p = fmaf(p, r, 1.3333558146428443e-3f);
    p = fmaf(p, r, 9.6181291076284772e-3f);
    p = fmaf(p, r, 5.5504108664821580e-2f);
    p = fmaf(p, r, 2.4022650695910072e-1f);
    p = fmaf(p, r, 6.9314718055994531e-1f);
    p = fmaf(p, r, 1.0f);
    int   i = (int)fl;
    float s = __int_as_float((i + 127) << 23);
    return p * s;
}

// ---------------------------------------------------------------------------
// K_detect: decide whether sample_inds is int64 or int32.
// Scans the first 8192 32-bit words (32 KB — safe under both layouts).
// If the buffer is int64 (values < 2^31), every odd word is 0.
// ---------------------------------------------------------------------------
__global__ void k_detect(const unsigned int* __restrict__ w) {
    unsigned acc = 0;
    for (int i = threadIdx.x; i < 4096; i += 256) acc |= w[2 * i + 1];
    #pragma unroll
    for (int o = 16; o; o >>= 1) acc |= __shfl_xor_sync(0xFFFFFFFFu, acc, o);
    __shared__ unsigned sh[8];
    if ((threadIdx.x & 31) == 0) sh[threadIdx.x >> 5] = acc;
    __syncthreads();
    if (threadIdx.x == 0) {
        unsigned t = 0;
        #pragma unroll
        for (int i = 0; i < 8; i++) t |= sh[i];
        g_is64 = (t == 0) ? 1 : 0;
    }
}

// ---------------------------------------------------------------------------
// K0: zero accumulators
// ---------------------------------------------------------------------------
__global__ void k_zero() {
    int i = blockIdx.x * blockDim.x + threadIdx.x;
    if (i < TV) { g_neg_sum[i] = 0.0f; g_row_loss[i] = 0.0f; }
}

// ---------------------------------------------------------------------------
// K1: gather V pixels per (image,class) pair, L2-normalize along C, store bf16.
// One block per sample (8192 blocks), 256 threads = one channel each.
// ---------------------------------------------------------------------------
__global__ void k_gather(const float* __restrict__ features,
                         const int* __restrict__ batch_inds,
                         const void* __restrict__ sample_inds) {
    int i = blockIdx.x;          // sample index 0..8191
    int c = threadIdx.x;         // channel
    int t = i >> 8;
    int v = i & 255;
    int b = batch_inds[t] & (NIMG - 1);   // defensive clamp (N=8 power of two)

    long long s;
    if (g_is64) s = ((const long long*)sample_inds)[t * VV + v];
    else        s = (long long)((const int*)sample_inds)[t * VV + v];
    if (s < 0) s = 0;
    if (s >= HWDIM) s = HWDIM - 1;

    float f = features[((size_t)b * CDIM + c) * HWDIM + (size_t)s];

    // block reduce sum of squares
    float ss = f * f;
    #pragma unroll
    for (int o = 16; o; o >>= 1) ss += __shfl_xor_sync(0xFFFFFFFFu, ss, o);
    __shared__ float wsum[8];
    __shared__ float tot;
    if ((c & 31) == 0) wsum[c >> 5] = ss;
    __syncthreads();
    if (c < 8) {
        float w = wsum[c];
        #pragma unroll
        for (int o = 4; o; o >>= 1) w += __shfl_xor_sync(0xFFu, w, o);
        if (c == 0) tot = w;
    }
    __syncthreads();

    float inv = 1.0f / fmaxf(sqrtf(tot), 1e-12f);
    g_feats[(size_t)i * CDIM + c] = __float2bfloat16(f * inv);
}

// ---------------------------------------------------------------------------
// Shared GEMM machinery: 128x128 tile, 8 warps in 2x4 (row x col) layout,
// each warp 64x32 via 4x4 grid of m16n8k16 bf16 mma.
// ---------------------------------------------------------------------------
__device__ __forceinline__ void load_tile(__nv_bfloat16* sm, int rowBase, int tid) {
    const uint4* g = (const uint4*)g_feats;  // 8 bf16 per uint4, 32 uint4 per row
    #pragma unroll
    for (int x = 0; x < 16; x++) {
        int idx = tid + x * 256;
        int row = idx >> 5;
        int u   = idx & 31;
        uint4 val = g[(((size_t)(rowBase + row)) << 5) + u];
        *(uint4*)(sm + row * RS + u * 8) = val;
    }
}

__device__ __forceinline__ void ldmA(uint32_t a[4], const __nv_bfloat16* base,
                                     int rowBase, int k0, int lane) {
    int row = rowBase + (lane & 15);
    int col = k0 + ((lane >> 4) << 3);
    uint32_t addr = (uint32_t)__cvta_generic_to_shared(base + row * RS + col);
    asm volatile("ldmatrix.sync.aligned.m8n8.x4.shared.b16 {%0,%1,%2,%3}, [%4];"
                 : "=r"(a[0]), "=r"(a[1]), "=r"(a[2]), "=r"(a[3]) : "r"(addr));
}

__device__ __forceinline__ void ldmB(uint32_t b[2], const __nv_bfloat16* base,
                                     int nBase, int k0, int lane) {
    int l   = lane & 15;
    int row = nBase + (l & 7);
    int col = k0 + ((l >> 3) << 3);
    uint32_t addr = (uint32_t)__cvta_generic_to_shared(base + row * RS + col);
    asm volatile("ldmatrix.sync.aligned.m8n8.x2.shared.b16 {%0,%1}, [%2];"
                 : "=r"(b[0]), "=r"(b[1]) : "r"(addr));
}

__device__ __forceinline__ void mma16816(float c[4], const uint32_t a[4], const uint32_t b[2]) {
    asm volatile("mma.sync.aligned.m16n8k16.row.col.f32.bf16.bf16.f32 "
                 "{%0,%1,%2,%3},{%4,%5,%6,%7},{%8,%9},{%0,%1,%2,%3};"
                 : "+f"(c[0]), "+f"(c[1]), "+f"(c[2]), "+f"(c[3])
                 : "r"(a[0]), "r"(a[1]), "r"(a[2]), "r"(a[3]), "r"(b[0]), "r"(b[1]));
}

__device__ __forceinline__ void gemm_tile(float acc[4][4][4],
                                          const __nv_bfloat16* sA,
                                          const __nv_bfloat16* sB,
                                          int wr, int wc, int lane) {
    #pragma unroll
    for (int ks = 0; ks < 16; ks++) {
        int k0 = ks * 16;
        uint32_t a[4][4];
        uint32_t b[4][2];
        #pragma unroll
        for (int mt = 0; mt < 4; mt++) ldmA(a[mt], sA, wr * 64 + mt * 16, k0, lane);
        #pragma unroll
        for (int nt = 0; nt < 4; nt++) ldmB(b[nt], sB, wc * 32 + nt * 8, k0, lane);
        #pragma unroll
        for (int mt = 0; mt < 4; mt++)
            #pragma unroll
            for (int nt = 0; nt < 4; nt++)
                mma16816(acc[mt][nt], a[mt], b[nt]);
    }
}

// ---------------------------------------------------------------------------
// K2: neg_sum[i] = sum over different-label columns of exp(dot_ij - 2)
// grid (4, 64): y = row tile, x = group of 16 column tiles.
// ---------------------------------------------------------------------------
extern "C" __global__ void __launch_bounds__(256, 1)
k_negsum(const int* __restrict__ labels) {
    extern __shared__ __align__(16) char dynsm[];
    __nv_bfloat16* sA = (__nv_bfloat16*)dynsm;
    __nv_bfloat16* sB = sA + TILE * RS;

    int rt   = blockIdx.y;
    int Lr   = labels[rt >> 1];
    int tid  = threadIdx.x;
    int lane = tid & 31;
    int wid  = tid >> 5;
    int wr   = wid >> 2;   // 0..1
    int wc   = wid & 3;    // 0..3

    load_tile(sA, rt * TILE, tid);

    float rowAcc[4][2];
    #pragma unroll
    for (int mt = 0; mt < 4; mt++) { rowAcc[mt][0] = 0.0f; rowAcc[mt][1] = 0.0f; }

    int ct0 = blockIdx.x * 16;
    for (int ct = ct0; ct < ct0 + 16; ct++) {
        int Lc = labels[ct >> 1];
        if (Lc == Lr) continue;           // positive (or self) tile: no contribution
        __syncthreads();                  // protect sB from previous iteration readers
        load_tile(sB, ct * TILE, tid);
        __syncthreads();

        float acc[4][4][4];
        #pragma unroll
        for (int mt = 0; mt < 4; mt++)
            #pragma unroll
            for (int nt = 0; nt < 4; nt++)
                #pragma unroll
                for (int q = 0; q < 4; q++) acc[mt][nt][q] = 0.0f;

        gemm_tile(acc, sA, sB, wr, wc, lane);

        // epilogue: exp(2a - 2), accumulate per-row
        #pragma unroll
        for (int mt = 0; mt < 4; mt++) {
            float s0 = 0.0f, s1 = 0.0f;
            #pragma unroll
            for (int nt = 0; nt < 4; nt++) {
                s0 += fexp(fmaf(2.0f, acc[mt][nt][0], -2.0f));
                s0 += fexp(fmaf(2.0f, acc[mt][nt][1], -2.0f));
                s1 += fexp(fmaf(2.0f, acc[mt][nt][2], -2.0f));
                s1 += fexp(fmaf(2.0f, acc[mt][nt][3], -2.0f));
            }
            rowAcc[mt][0] += s0;
            rowAcc[mt][1] += s1;
        }
    }

    // reduce across the 4 lanes sharing each row, then one atomic per row
    #pragma unroll
    for (int mt = 0; mt < 4; mt++)
        #pragma unroll
        for (int h = 0; h < 2; h++) {
            float v = rowAcc[mt][h];
            v += __shfl_xor_sync(0xFFFFFFFFu, v, 1);
            v += __shfl_xor_sync(0xFFFFFFFFu, v, 2);
            if ((lane & 3) == 0) {
                int row = rt * TILE + wr * 64 + mt * 16 + (lane >> 2) + h * 8;
                atomicAdd(&g_neg_sum[row], v);
            }
        }
}

// ---------------------------------------------------------------------------
// K3: positive pairs. grid (64, 64), early-exit on label mismatch (~95%).
// row_loss[i] += sum over positives j of [ l - log(S_i) - x + x^2/2 ],
// x = exp(l)/S_i  (log1p expansion, x <= 0.008).
// ---------------------------------------------------------------------------
extern "C" __global__ void __launch_bounds__(256, 1)
k_pos(const int* __restrict__ labels) {
    int rt = blockIdx.y;
    int ct = blockIdx.x;
    if (labels[rt >> 1] != labels[ct >> 1]) return;

    extern __shared__ __align__(16) char dynsm[];
    __nv_bfloat16* sA = (__nv_bfloat16*)dynsm;
    __nv_bfloat16* sB = sA + TILE * RS;

    int tid  = threadIdx.x;
    int lane = tid & 31;
    int wid  = tid >> 5;
    int wr   = wid >> 2;
    int wc   = wid & 3;

    load_tile(sA, rt * TILE, tid);
    load_tile(sB, ct * TILE, tid);
    __syncthreads();

    float acc[4][4][4];
    #pragma unroll
    for (int mt = 0; mt < 4; mt++)
        #pragma unroll
        for (int nt = 0; nt < 4; nt++)
            #pragma unroll
            for (int q = 0; q < 4; q++) acc[mt][nt][q] = 0.0f;

    gemm_tile(acc, sA, sB, wr, wc, lane);

    #pragma unroll
    for (int mt = 0; mt < 4; mt++) {
        int row0 = rt * TILE + wr * 64 + mt * 16 + (lane >> 2);
        float tAcc[2];
        #pragma unroll
        for (int h = 0; h < 2; h++) {
            int row    = row0 + h * 8;
            float S    = g_neg_sum[row];
            float logS = __logf(S);
            float invS = 1.0f / S;
            float sum  = 0.0f;
            #pragma unroll
            for (int nt = 0; nt < 4; nt++) {
                int colBase = ct * TILE + wc * 32 + nt * 8 + ((lane & 3) << 1);
                #pragma unroll
                for (int cc = 0; cc < 2; cc++) {
                    int col = colBase + cc;
                    if (col != row) {
                        float a = acc[mt][nt][h * 2 + cc];
                        float l = fmaf(2.0f, a, -2.0f);
                        float e = fexp(l);
                        float x = e * invS;
                        sum += l - logS - x + 0.5f * x * x;
                    }
                }
            }
            tAcc[h] = sum;
        }
        #pragma unroll
        for (int h = 0; h < 2; h++) {
            float v = tAcc[h];
            v += __shfl_xor_sync(0xFFFFFFFFu, v, 1);
            v += __shfl_xor_sync(0xFFFFFFFFu, v, 2);
            if ((lane & 3) == 0) {
                int row = row0 + h * 8;
                atomicAdd(&g_row_loss[row], v);
            }
        }
    }
}

// ---------------------------------------------------------------------------
// K4: final reduction: loss = -mean_i( row_loss[i] / pos_count[img(i)] )
// pos_count[img] = (#images with same label)*V - 1
// ---------------------------------------------------------------------------
__global__ void k_final(const int* __restrict__ labels, float* __restrict__ out) {
    __shared__ int   lab[TT];
    __shared__ float invpc[TT];
    __shared__ float ws[8];
    int tid = threadIdx.x;
    if (tid < TT) lab[tid] = labels[tid];
    __syncthreads();
    if (tid < TT) {
        int ns = 0;
        #pragma unroll
        for (int j = 0; j < TT; j++) ns += (lab[j] == lab[tid]);
        invpc[tid] = 1.0f / (float)(ns * VV - 1);
    }
    __syncthreads();

    float s = 0.0f;
    for (int i = tid; i < TV; i += 256) s += g_row_loss[i] * invpc[i >> 8];
    #pragma unroll
    for (int o = 16; o; o >>= 1) s += __shfl_xor_sync(0xFFFFFFFFu, s, o);
    if ((tid & 31) == 0) ws[tid >> 5] = s;
    __syncthreads();
    if (tid == 0) {
        float t = 0.0f;
        #pragma unroll
        for (int w = 0; w < 8; w++) t += ws[w];
        out[0] = -(t / (float)TV);
    }
}

// ---------------------------------------------------------------------------
extern "C" void kernel_launch(void* const* d_in, const int* in_sizes, int n_in,
                              void* d_out, int out_size) {
    const float* features    = (const float*)d_in[0];
    const int*   batch_inds  = (const int*)d_in[1];
    const void*  sample_inds = (const void*)d_in[2];
    const int*   labels      = (const int*)d_in[3];
    float*       out         = (float*)d_out;

    static bool attr_set = false;
    if (!attr_set) {
        cudaFuncSetAttribute(k_negsum, cudaFuncAttributeMaxDynamicSharedMemorySize, SMEM_BYTES);
        cudaFuncSetAttribute(k_pos,    cudaFuncAttributeMaxDynamicSharedMemorySize, SMEM_BYTES);
        attr_set = true;
    }

    k_detect<<<1, 256>>>((const unsigned int*)sample_inds);
    k_zero<<<(TV + 255) / 256, 256>>>();
    k_gather<<<TV, 256>>>(features, batch_inds, sample_inds);
    k_negsum<<<dim3(4, NTILES), 256, SMEM_BYTES>>>(labels);
    k_pos<<<dim3(NTILES, NTILES), 256, SMEM_BYTES>>>(labels);
    k_final<<<1, 256>>>(labels, out);
}

// round 4
// speedup vs baseline: 1.0288x; 1.0288x over previous
#include <cuda_runtime.h>
#include <cuda_bf16.h>
#include <cstdint>

// Problem constants
#define NIMG   8
#define CDIM   256
#define HWDIM  9216
#define TT     32
#define VV     256
#define TV     8192      // TT*VV rows
#define TILE   128
#define NTILES 64        // TV / TILE
#define RS     264       // padded smem row stride in bf16 elements (256 + 8)

#define SMEM_BYTES_POS (2 * TILE * RS * 2)   // k_pos: A + B tile
#define SMEM_BYTES_NEG (3 * TILE * RS * 2)   // k_negsum: A + B0 + B1 (202752 B)

// Persistent device scratch (no dynamic allocation allowed)
__device__ __nv_bfloat16 g_feats[(size_t)TV * CDIM];  // normalized features, bf16 row-major
__device__ float g_neg_sum[TV];
__device__ float g_row_loss[TV];
__device__ int   g_is64;                 // sample_inds stored as int64? (detected at runtime)

// MUFU-based exp2 (runs on its own pipe; overlaps FMA/tensor work)
__device__ __forceinline__ float fexp2(float x) {
    float r;
    asm("ex2.approx.f32 %0, %1;" : "=f"(r) : "f"(x));
    return r;
}
#define LOG2E_X2 2.8853900817779268f   // 2*log2(e): exp(2a-2) = 2^(a*L - L)

// ---------------------------------------------------------------------------
// K_detect: decide whether sample_inds is int64 or int32.
// ---------------------------------------------------------------------------
__global__ void k_detect(const unsigned int* __restrict__ w) {
    unsigned acc = 0;
    for (int i = threadIdx.x; i < 4096; i += 256) acc |= w[2 * i + 1];
    #pragma unroll
    for (int o = 16; o; o >>= 1) acc |= __shfl_xor_sync(0xFFFFFFFFu, acc, o);
    __shared__ unsigned sh[8];
    if ((threadIdx.x & 31) == 0) sh[threadIdx.x >> 5] = acc;
    __syncthreads();
    if (threadIdx.x == 0) {
        unsigned t = 0;
        #pragma unroll
        for (int i = 0; i < 8; i++) t |= sh[i];
        g_is64 = (t == 0) ? 1 : 0;
    }
}

__global__ void k_zero() {
    int i = blockIdx.x * blockDim.x + threadIdx.x;
    if (i < TV) { g_neg_sum[i] = 0.0f; g_row_loss[i] = 0.0f; }
}

// ---------------------------------------------------------------------------
// K1: gather + L2-normalize -> bf16
// ---------------------------------------------------------------------------
__global__ void k_gather(const float* __restrict__ features,
                         const int* __restrict__ batch_inds,
                         const void* __restrict__ sample_inds) {
    int i = blockIdx.x;
    int c = threadIdx.x;
    int t = i >> 8;
    int v = i & 255;
    int b = batch_inds[t] & (NIMG - 1);

    long long s;
    if (g_is64) s = ((const long long*)sample_inds)[t * VV + v];
    else        s = (long long)((const int*)sample_inds)[t * VV + v];
    if (s < 0) s = 0;
    if (s >= HWDIM) s = HWDIM - 1;

    float f = features[((size_t)b * CDIM + c) * HWDIM + (size_t)s];

    float ss = f * f;
    #pragma unroll
    for (int o = 16; o; o >>= 1) ss += __shfl_xor_sync(0xFFFFFFFFu, ss, o);
    __shared__ float wsum[8];
    __shared__ float tot;
    if ((c & 31) == 0) wsum[c >> 5] = ss;
    __syncthreads();
    if (c < 8) {
        float w = wsum[c];
        #pragma unroll
        for (int o = 4; o; o >>= 1) w += __shfl_xor_sync(0xFFu, w, o);
        if (c == 0) tot = w;
    }
    __syncthreads();

    float inv = 1.0f / fmaxf(sqrtf(tot), 1e-12f);
    g_feats[(size_t)i * CDIM + c] = __float2bfloat16(f * inv);
}

// ---------------------------------------------------------------------------
// mma.sync machinery
// ---------------------------------------------------------------------------
__device__ __forceinline__ void ldmA(uint32_t a[4], const __nv_bfloat16* base,
                                     int rowBase, int k0, int lane) {
    int row = rowBase + (lane & 15);
    int col = k0 + ((lane >> 4) << 3);
    uint32_t addr = (uint32_t)__cvta_generic_to_shared(base + row * RS + col);
    asm volatile("ldmatrix.sync.aligned.m8n8.x4.shared.b16 {%0,%1,%2,%3}, [%4];"
                 : "=r"(a[0]), "=r"(a[1]), "=r"(a[2]), "=r"(a[3]) : "r"(addr));
}
__device__ __forceinline__ void ldmB(uint32_t b[2], const __nv_bfloat16* base,
                                     int nBase, int k0, int lane) {
    int l   = lane & 15;
    int row = nBase + (l & 7);
    int col = k0 + ((l >> 3) << 3);
    uint32_t addr = (uint32_t)__cvta_generic_to_shared(base + row * RS + col);
    asm volatile("ldmatrix.sync.aligned.m8n8.x2.shared.b16 {%0,%1}, [%2];"
                 : "=r"(b[0]), "=r"(b[1]) : "r"(addr));
}
__device__ __forceinline__ void mma16816(float c[4], const uint32_t a[4], const uint32_t b[2]) {
    asm volatile("mma.sync.aligned.m16n8k16.row.col.f32.bf16.bf16.f32 "
                 "{%0,%1,%2,%3},{%4,%5,%6,%7},{%8,%9},{%0,%1,%2,%3};"
                 : "+f"(c[0]), "+f"(c[1]), "+f"(c[2]), "+f"(c[3])
                 : "r"(a[0]), "r"(a[1]), "r"(a[2]), "r"(a[3]), "r"(b[0]), "r"(b[1]));
}

// ---------------------------------------------------------------------------
// K2: neg_sum via two warp-groups specialized on tile parity.
// 512 threads = 2 groups x 8 warps. Group g handles negative tiles g, g+2, ...
// with its own B buffer + named barrier, so one group's MMA phase (tensor+LDSM)
// overlaps the other group's epilogue (FMA+MUFU) and B load.
// Each group: 8 warps as 2(row)x4(col), warp tile 64x16, two 64-col passes.
// ---------------------------------------------------------------------------
extern "C" __global__ void __launch_bounds__(512, 1)
k_negsum(const int* __restrict__ labels) {
    extern __shared__ __align__(16) char dynsm[];
    __nv_bfloat16* sA  = (__nv_bfloat16*)dynsm;
    __nv_bfloat16* sB0 = sA + TILE * RS;
    __nv_bfloat16* sB1 = sB0 + TILE * RS;

    __shared__ int sList[32];
    __shared__ int sCnt;

    int tid  = threadIdx.x;
    int lane = tid & 31;
    int wid  = tid >> 5;
    int g    = wid >> 3;        // group 0/1
    int gw   = wid & 7;         // warp within group
    int wr   = gw >> 2;         // 0..1  (64-row slab)
    int wc   = gw & 3;          // 0..3  (16-col slab within 64-col half)
    int rt   = blockIdx.y;
    int Lr   = labels[rt >> 1];

    if (tid == 0) {
        int cnt = 0, ct0 = blockIdx.x * 32;
        for (int ct = ct0; ct < ct0 + 32; ct++)
            if (labels[ct >> 1] != Lr) sList[cnt++] = ct;
        sCnt = cnt;
    }
    // A tile load, all 512 threads
    {
        const uint4* gm = (const uint4*)g_feats;
        #pragma unroll
        for (int x = 0; x < 8; x++) {
            int idx = tid + x * 512;
            int row = idx >> 5, u = idx & 31;
            *(uint4*)(sA + row * RS + u * 8) =
                gm[(((size_t)(rt * TILE + row)) << 5) + u];
        }
    }
    __syncthreads();
    int cnt = sCnt;

    __nv_bfloat16* sB = g ? sB1 : sB0;
    int gtid = tid & 255;
    int barid = 1 + g;
    float rowAcc[4][2] = {};

    for (int j = g; j < cnt; j += 2) {
        // group loads its B tile
        {
            const uint4* gm = (const uint4*)g_feats;
            int rb = sList[j] * TILE;
            #pragma unroll
            for (int x = 0; x < 16; x++) {
                int idx = gtid + x * 256;
                int row = idx >> 5, u = idx & 31;
                *(uint4*)(sB + row * RS + u * 8) =
                    gm[(((size_t)(rb + row)) << 5) + u];
            }
        }
        asm volatile("bar.sync %0, 256;" :: "r"(barid) : "memory");

        #pragma unroll
        for (int half = 0; half < 2; half++) {
            float acc[4][2][4];
            #pragma unroll
            for (int mt = 0; mt < 4; mt++)
                #pragma unroll
                for (int nt = 0; nt < 2; nt++)
                    #pragma unroll
                    for (int q = 0; q < 4; q++) acc[mt][nt][q] = 0.0f;

            #pragma unroll
            for (int ks = 0; ks < 16; ks++) {
                int k0 = ks * 16;
                uint32_t a[4][4], b[2][2];
                #pragma unroll
                for (int mt = 0; mt < 4; mt++)
                    ldmA(a[mt], sA, wr * 64 + mt * 16, k0, lane);
                #pragma unroll
                for (int nt = 0; nt < 2; nt++)
                    ldmB(b[nt], sB, half * 64 + wc * 16 + nt * 8, k0, lane);
                #pragma unroll
                for (int mt = 0; mt < 4; mt++)
                    #pragma unroll
                    for (int nt = 0; nt < 2; nt++)
                        mma16816(acc[mt][nt], a[mt], b[nt]);
            }

            // epilogue: exp(2a-2) = 2^(a*L - L), MUFU ex2
            #pragma unroll
            for (int mt = 0; mt < 4; mt++)
                #pragma unroll
                for (int h = 0; h < 2; h++) {
                    float s = 0.0f;
                    #pragma unroll
                    for (int nt = 0; nt < 2; nt++) {
                        s += fexp2(fmaf(acc[mt][nt][h * 2 + 0], LOG2E_X2, -LOG2E_X2));
                        s += fexp2(fmaf(acc[mt][nt][h * 2 + 1], LOG2E_X2, -LOG2E_X2));
                    }
                    rowAcc[mt][h] += s;
                }
        }
        asm volatile("bar.sync %0, 256;" :: "r"(barid) : "memory");
    }

    // reduce 4 lanes per row, one atomic per (warp,mt,h)
    #pragma unroll
    for (int mt = 0; mt < 4; mt++)
        #pragma unroll
        for (int h = 0; h < 2; h++) {
            float v = rowAcc[mt][h];
            v += __shfl_xor_sync(0xFFFFFFFFu, v, 1);
            v += __shfl_xor_sync(0xFFFFFFFFu, v, 2);
            if ((lane & 3) == 0 && cnt > 0) {
                int row = rt * TILE + wr * 64 + mt * 16 + (lane >> 2) + h * 8;
                atomicAdd(&g_neg_sum[row], v);
            }
        }
}

// ---------------------------------------------------------------------------
// K3: positive pairs (early-exit on label mismatch). 256 threads, 8 warps 2x4,
// warp tile 64x32 (as in R2 — register budget is fine at 256 threads).
// ---------------------------------------------------------------------------
__device__ __forceinline__ void load_tile(__nv_bfloat16* smx, int rowBase, int tid) {
    const uint4* gm = (const uint4*)g_feats;
    #pragma unroll
    for (int x = 0; x < 16; x++) {
        int idx = tid + x * 256;
        int row = idx >> 5;
        int u   = idx & 31;
        *(uint4*)(smx + row * RS + u * 8) = gm[(((size_t)(rowBase + row)) << 5) + u];
    }
}

extern "C" __global__ void __launch_bounds__(256, 1)
k_pos(const int* __restrict__ labels) {
    int rt = blockIdx.y;
    int ct = blockIdx.x;
    if (labels[rt >> 1] != labels[ct >> 1]) return;

    extern __shared__ __align__(16) char dynsm[];
    __nv_bfloat16* sA = (__nv_bfloat16*)dynsm;
    __nv_bfloat16* sB = sA + TILE * RS;

    int tid  = threadIdx.x;
    int lane = tid & 31;
    int wid  = tid >> 5;
    int wr   = wid >> 2;
    int wc   = wid & 3;

    load_tile(sA, rt * TILE, tid);
    load_tile(sB, ct * TILE, tid);
    __syncthreads();

    float acc[4][4][4];
    #pragma unroll
    for (int mt = 0; mt < 4; mt++)
        #pragma unroll
        for (int nt = 0; nt < 4; nt++)
            #pragma unroll
            for (int q = 0; q < 4; q++) acc[mt][nt][q] = 0.0f;

    #pragma unroll
    for (int ks = 0; ks < 16; ks++) {
        int k0 = ks * 16;
        uint32_t a[4][4], b[4][2];
        #pragma unroll
        for (int mt = 0; mt < 4; mt++) ldmA(a[mt], sA, wr * 64 + mt * 16, k0, lane);
        #pragma unroll
        for (int nt = 0; nt < 4; nt++) ldmB(b[nt], sB, wc * 32 + nt * 8, k0, lane);
        #pragma unroll
        for (int mt = 0; mt < 4; mt++)
            #pragma unroll
            for (int nt = 0; nt < 4; nt++)
                mma16816(acc[mt][nt], a[mt], b[nt]);
    }

    #pragma unroll
    for (int mt = 0; mt < 4; mt++) {
        int row0 = rt * TILE + wr * 64 + mt * 16 + (lane >> 2);
        float tAcc[2];
        #pragma unroll
        for (int h = 0; h < 2; h++) {
            int row    = row0 + h * 8;
            float S    = g_neg_sum[row];
            float logS = __logf(S);
            float invS = 1.0f / S;
            float sum  = 0.0f;
            #pragma unroll
            for (int nt = 0; nt < 4; nt++) {
                int colBase = ct * TILE + wc * 32 + nt * 8 + ((lane & 3) << 1);
                #pragma unroll
                for (int cc = 0; cc < 2; cc++) {
                    int col = colBase + cc;
                    if (col != row) {
                        float a = acc[mt][nt][h * 2 + cc];
                        float l = fmaf(2.0f, a, -2.0f);
                        float e = fexp2(l * 1.4426950408889634f);
                        float x = e * invS;
                        sum += l - logS - x + 0.5f * x * x;
                    }
                }
            }
            tAcc[h] = sum;
        }
        #pragma unroll
        for (int h = 0; h < 2; h++) {
            float v = tAcc[h];
            v += __shfl_xor_sync(0xFFFFFFFFu, v, 1);
            v += __shfl_xor_sync(0xFFFFFFFFu, v, 2);
            if ((lane & 3) == 0) {
                int row = row0 + h * 8;
                atomicAdd(&g_row_loss[row], v);
            }
        }
    }
}

// ---------------------------------------------------------------------------
// K4: final reduction
// ---------------------------------------------------------------------------
__global__ void k_final(const int* __restrict__ labels, float* __restrict__ out) {
    __shared__ int   lab[TT];
    __shared__ float invpc[TT];
    __shared__ float ws[8];
    int tid = threadIdx.x;
    if (tid < TT) lab[tid] = labels[tid];
    __syncthreads();
    if (tid < TT) {
        int ns = 0;
        #pragma unroll
        for (int j = 0; j < TT; j++) ns += (lab[j] == lab[tid]);
        invpc[tid] = 1.0f / (float)(ns * VV - 1);
    }
    __syncthreads();

    float s = 0.0f;
    for (int i = tid; i < TV; i += 256) s += g_row_loss[i] * invpc[i >> 8];
    #pragma unroll
    for (int o = 16; o; o >>= 1) s += __shfl_xor_sync(0xFFFFFFFFu, s, o);
    if ((tid & 31) == 0) ws[tid >> 5] = s;
    __syncthreads();
    if (tid == 0) {
        float t = 0.0f;
        #pragma unroll
        for (int w = 0; w < 8; w++) t += ws[w];
        out[0] = -(t / (float)TV);
    }
}

// ---------------------------------------------------------------------------
extern "C" void kernel_launch(void* const* d_in, const int* in_sizes, int n_in,
                              void* d_out, int out_size) {
    const float* features    = (const float*)d_in[0];
    const int*   batch_inds  = (const int*)d_in[1];
    const void*  sample_inds = (const void*)d_in[2];
    const int*   labels      = (const int*)d_in[3];
    float*       out         = (float*)d_out;

    static bool attr_set = false;
    if (!attr_set) {
        cudaFuncSetAttribute(k_negsum, cudaFuncAttributeMaxDynamicSharedMemorySize, SMEM_BYTES_NEG);
        cudaFuncSetAttribute(k_pos,    cudaFuncAttributeMaxDynamicSharedMemorySize, SMEM_BYTES_POS);
        attr_set = true;
    }

    k_detect<<<1, 256>>>((const unsigned int*)sample_inds);
    k_zero<<<(TV + 255) / 256, 256>>>();
    k_gather<<<TV, 256>>>(features, batch_inds, sample_inds);
    k_negsum<<<dim3(2, NTILES), 512, SMEM_BYTES_NEG>>>(labels);
    k_pos<<<dim3(NTILES, NTILES), 256, SMEM_BYTES_POS>>>(labels);
    k_final<<<1, 256>>>(labels, out);
}

// round 5
// speedup vs baseline: 1.7697x; 1.7202x over previous
#include <cuda_runtime.h>
#include <cuda_fp16.h>
#include <cstdint>

// Problem constants
#define NIMG   8
#define CDIM   256
#define HWDIM  9216
#define TT     32
#define VV     256
#define TV     8192      // TT*VV rows
#define TILE   128
#define NTILES 64        // TV / TILE

// k_pos smem: full 128x256 A+B tiles, padded stride 264 halves
#define RS     264
#define SMEM_BYTES_POS (2 * TILE * RS * 2)

// k_negpair smem: two 128x128 chunks, padded stride 136 halves (272 B)
#define CRS    136
#define CHUNK_BYTES (TILE * CRS * 2)          // 34816
#define SMEM_BYTES_NEG (2 * CHUNK_BYTES)      // 69632

#define LOG2E    1.4426950408889634f
#define LOG2E_X2 2.8853900817779268f          // exp(2a-2) = 2^(a*L2 - L2)

// Persistent device scratch
__device__ __half g_feats[(size_t)TV * CDIM];  // normalized features, fp16 row-major
__device__ float g_neg_sum[TV];
__device__ float g_row_loss[TV];
__device__ int   g_is64;

__device__ __forceinline__ float fexp2(float x) {
    float r;
    asm("ex2.approx.f32 %0, %1;" : "=f"(r) : "f"(x));
    return r;
}

// ---------------------------------------------------------------------------
// K_detect: int64 vs int32 sample_inds
// ---------------------------------------------------------------------------
__global__ void k_detect(const unsigned int* __restrict__ w) {
    unsigned acc = 0;
    for (int i = threadIdx.x; i < 4096; i += 256) acc |= w[2 * i + 1];
    #pragma unroll
    for (int o = 16; o; o >>= 1) acc |= __shfl_xor_sync(0xFFFFFFFFu, acc, o);
    __shared__ unsigned sh[8];
    if ((threadIdx.x & 31) == 0) sh[threadIdx.x >> 5] = acc;
    __syncthreads();
    if (threadIdx.x == 0) {
        unsigned t = 0;
        #pragma unroll
        for (int i = 0; i < 8; i++) t |= sh[i];
        g_is64 = (t == 0) ? 1 : 0;
    }
}

__global__ void k_zero() {
    int i = blockIdx.x * blockDim.x + threadIdx.x;
    if (i < TV) { g_neg_sum[i] = 0.0f; g_row_loss[i] = 0.0f; }
}

// ---------------------------------------------------------------------------
// K1: gather + L2-normalize -> fp16
// ---------------------------------------------------------------------------
__global__ void k_gather(const float* __restrict__ features,
                         const int* __restrict__ batch_inds,
                         const void* __restrict__ sample_inds) {
    int i = blockIdx.x;
    int c = threadIdx.x;
    int t = i >> 8;
    int v = i & 255;
    int b = batch_inds[t] & (NIMG - 1);

    long long s;
    if (g_is64) s = ((const long long*)sample_inds)[t * VV + v];
    else        s = (long long)((const int*)sample_inds)[t * VV + v];
    if (s < 0) s = 0;
    if (s >= HWDIM) s = HWDIM - 1;

    float f = features[((size_t)b * CDIM + c) * HWDIM + (size_t)s];

    float ss = f * f;
    #pragma unroll
    for (int o = 16; o; o >>= 1) ss += __shfl_xor_sync(0xFFFFFFFFu, ss, o);
    __shared__ float wsum[8];
    __shared__ float tot;
    if ((c & 31) == 0) wsum[c >> 5] = ss;
    __syncthreads();
    if (c < 8) {
        float w = wsum[c];
        #pragma unroll
        for (int o = 4; o; o >>= 1) w += __shfl_xor_sync(0xFFu, w, o);
        if (c == 0) tot = w;
    }
    __syncthreads();

    float inv = 1.0f / fmaxf(sqrtf(tot), 1e-12f);
    g_feats[(size_t)i * CDIM + c] = __float2half(f * inv);
}

// ---------------------------------------------------------------------------
// ldmatrix helpers (shared by both GEMM kernels; stride in halves)
// ---------------------------------------------------------------------------
template<int STRIDE>
__device__ __forceinline__ void ldmA(uint32_t a[4], const __half* base,
                                     int rowBase, int k0, int lane) {
    int row = rowBase + (lane & 15);
    int col = k0 + ((lane >> 4) << 3);
    uint32_t addr = (uint32_t)__cvta_generic_to_shared(base + row * STRIDE + col);
    asm volatile("ldmatrix.sync.aligned.m8n8.x4.shared.b16 {%0,%1,%2,%3}, [%4];"
                 : "=r"(a[0]), "=r"(a[1]), "=r"(a[2]), "=r"(a[3]) : "r"(addr));
}
template<int STRIDE>
__device__ __forceinline__ void ldmB(uint32_t b[2], const __half* base,
                                     int nBase, int k0, int lane) {
    int l   = lane & 15;
    int row = nBase + (l & 7);
    int col = k0 + ((l >> 3) << 3);
    uint32_t addr = (uint32_t)__cvta_generic_to_shared(base + row * STRIDE + col);
    asm volatile("ldmatrix.sync.aligned.m8n8.x2.shared.b16 {%0,%1}, [%2];"
                 : "=r"(b[0]), "=r"(b[1]) : "r"(addr));
}

// f16 inputs, f16 accumulators (2x rate, half the acc registers)
__device__ __forceinline__ void mma_f16acc(uint32_t c[2], const uint32_t a[4],
                                           const uint32_t b[2]) {
    asm volatile("mma.sync.aligned.m16n8k16.row.col.f16.f16.f16.f16 "
                 "{%0,%1},{%2,%3,%4,%5},{%6,%7},{%0,%1};"
                 : "+r"(c[0]), "+r"(c[1])
                 : "r"(a[0]), "r"(a[1]), "r"(a[2]), "r"(a[3]), "r"(b[0]), "r"(b[1]));
}
// f16 inputs, f32 accumulators (k_pos: logits need higher fidelity downstream math anyway)
__device__ __forceinline__ void mma_f32acc(float c[4], const uint32_t a[4],
                                           const uint32_t b[2]) {
    asm volatile("mma.sync.aligned.m16n8k16.row.col.f32.f16.f16.f32 "
                 "{%0,%1,%2,%3},{%4,%5,%6,%7},{%8,%9},{%0,%1,%2,%3};"
                 : "+f"(c[0]), "+f"(c[1]), "+f"(c[2]), "+f"(c[3])
                 : "r"(a[0]), "r"(a[1]), "r"(a[2]), "r"(a[3]), "r"(b[0]), "r"(b[1]));
}

// ---------------------------------------------------------------------------
// K2 (k_negpair): one different-label tile PAIR (rt, ct), rt < ct, per block.
// Computes the 128x128 dot tile once; exp sums scattered to BOTH sides:
//   row sums -> g_neg_sum[rows of rt],  col sums -> g_neg_sum[rows of ct].
// K is processed in two 128-wide chunks so smem = 2 x 34 KB -> 2 CTAs/SM.
// 8 warps as 2(row) x 4(col); warp tile 64x32; f16 accumulators (32 regs).
// ---------------------------------------------------------------------------
extern "C" __global__ void __launch_bounds__(256, 2)
k_negpair(const int* __restrict__ labels) {
    int rt = blockIdx.y;
    int ct = blockIdx.x;
    if (ct <= rt) return;                       // strict upper triangle
    if (labels[rt >> 1] == labels[ct >> 1]) return;  // negatives only

    extern __shared__ __align__(16) char dynsm[];
    __half* sA = (__half*)dynsm;                // 128 x 128 chunk, stride CRS
    __half* sB = sA + TILE * CRS;

    int tid  = threadIdx.x;
    int lane = tid & 31;
    int wid  = tid >> 5;
    int wr   = wid >> 2;     // 0..1
    int wc   = wid & 3;      // 0..3

    uint32_t acc[4][4][2];   // [mt][nt][h] f16x2 accumulators
    #pragma unroll
    for (int mt = 0; mt < 4; mt++)
        #pragma unroll
        for (int nt = 0; nt < 4; nt++) { acc[mt][nt][0] = 0u; acc[mt][nt][1] = 0u; }

    #pragma unroll
    for (int kc = 0; kc < 2; kc++) {
        if (kc) __syncthreads();                // protect buffers before reload
        // load A(rt) and B(ct) K-chunks: 8 uint4 per thread each
        {
            const uint4* gm = (const uint4*)g_feats;   // 32 uint4 per 256-half row
            int kq = kc * 16;                           // uint4 offset of chunk
            #pragma unroll
            for (int x = 0; x < 8; x++) {
                int idx = tid + x * 256;
                int row = idx >> 4;                     // 16 uint4 per chunk row
                int u   = idx & 15;
                *(uint4*)(sA + row * CRS + u * 8) =
                    gm[(((size_t)(rt * TILE + row)) << 5) + kq + u];
                *(uint4*)(sB + row * CRS + u * 8) =
                    gm[(((size_t)(ct * TILE + row)) << 5) + kq + u];
            }
        }
        __syncthreads();

        #pragma unroll
        for (int ks = 0; ks < 8; ks++) {
            int k0 = ks * 16;
            uint32_t a[4][4], b[4][2];
            #pragma unroll
            for (int mt = 0; mt < 4; mt++)
                ldmA<CRS>(a[mt], sA, wr * 64 + mt * 16, k0, lane);
            #pragma unroll
            for (int nt = 0; nt < 4; nt++)
                ldmB<CRS>(b[nt], sB, wc * 32 + nt * 8, k0, lane);
            #pragma unroll
            for (int mt = 0; mt < 4; mt++)
                #pragma unroll
                for (int nt = 0; nt < 4; nt++)
                    mma_f16acc(acc[mt][nt], a[mt], b[nt]);
        }
    }

    // epilogue: v = exp(2a-2) for all 64 elements; accumulate row + col partials
    float rAcc[4][2] = {};   // [mt][h]   row partial (sum over this warp's 32 cols)
    float cAcc[4][2] = {};   // [nt][cc]  col partial (sum over this warp's 64 rows)
    #pragma unroll
    for (int mt = 0; mt < 4; mt++)
        #pragma unroll
        for (int nt = 0; nt < 4; nt++)
            #pragma unroll
            for (int h = 0; h < 2; h++) {
                __half2 p = *(__half2*)&acc[mt][nt][h];
                float a0 = __low2float(p), a1 = __high2float(p);
                float v0 = fexp2(fmaf(a0, LOG2E_X2, -LOG2E_X2));
                float v1 = fexp2(fmaf(a1, LOG2E_X2, -LOG2E_X2));
                rAcc[mt][h] += v0 + v1;
                cAcc[nt][0] += v0;
                cAcc[nt][1] += v1;
            }

    // row sums: lanes sharing a row differ in (lane&3) -> xor 1,2
    #pragma unroll
    for (int mt = 0; mt < 4; mt++)
        #pragma unroll
        for (int h = 0; h < 2; h++) {
            float v = rAcc[mt][h];
            v += __shfl_xor_sync(0xFFFFFFFFu, v, 1);
            v += __shfl_xor_sync(0xFFFFFFFFu, v, 2);
            if ((lane & 3) == 0) {
                int row = rt * TILE + wr * 64 + mt * 16 + (lane >> 2) + h * 8;
                atomicAdd(&g_neg_sum[row], v);
            }
        }
    // col sums: lanes sharing a col differ in (lane>>2) -> xor 4,8,16
    #pragma unroll
    for (int nt = 0; nt < 4; nt++)
        #pragma unroll
        for (int cc = 0; cc < 2; cc++) {
            float v = cAcc[nt][cc];
            v += __shfl_xor_sync(0xFFFFFFFFu, v, 4);
            v += __shfl_xor_sync(0xFFFFFFFFu, v, 8);
            v += __shfl_xor_sync(0xFFFFFFFFu, v, 16);
            if (lane < 4) {
                int col = ct * TILE + wc * 32 + nt * 8 + 2 * lane + cc;
                atomicAdd(&g_neg_sum[col], v);
            }
        }
}

// ---------------------------------------------------------------------------
// K3: positive pairs (early-exit on label mismatch). f32 accumulators.
// ---------------------------------------------------------------------------
__device__ __forceinline__ void load_tile(__half* smx, int rowBase, int tid) {
    const uint4* gm = (const uint4*)g_feats;
    #pragma unroll
    for (int x = 0; x < 16; x++) {
        int idx = tid + x * 256;
        int row = idx >> 5;
        int u   = idx & 31;
        *(uint4*)(smx + row * RS + u * 8) = gm[(((size_t)(rowBase + row)) << 5) + u];
    }
}

extern "C" __global__ void __launch_bounds__(256, 1)
k_pos(const int* __restrict__ labels) {
    int rt = blockIdx.y;
    int ct = blockIdx.x;
    if (labels[rt >> 1] != labels[ct >> 1]) return;

    extern __shared__ __align__(16) char dynsm[];
    __half* sA = (__half*)dynsm;
    __half* sB = sA + TILE * RS;

    int tid  = threadIdx.x;
    int lane = tid & 31;
    int wid  = tid >> 5;
    int wr   = wid >> 2;
    int wc   = wid & 3;

    load_tile(sA, rt * TILE, tid);
    load_tile(sB, ct * TILE, tid);
    __syncthreads();

    float acc[4][4][4];
    #pragma unroll
    for (int mt = 0; mt < 4; mt++)
        #pragma unroll
        for (int nt = 0; nt < 4; nt++)
            #pragma unroll
            for (int q = 0; q < 4; q++) acc[mt][nt][q] = 0.0f;

    #pragma unroll
    for (int ks = 0; ks < 16; ks++) {
        int k0 = ks * 16;
        uint32_t a[4][4], b[4][2];
        #pragma unroll
        for (int mt = 0; mt < 4; mt++) ldmA<RS>(a[mt], sA, wr * 64 + mt * 16, k0, lane);
        #pragma unroll
        for (int nt = 0; nt < 4; nt++) ldmB<RS>(b[nt], sB, wc * 32 + nt * 8, k0, lane);
        #pragma unroll
        for (int mt = 0; mt < 4; mt++)
            #pragma unroll
            for (int nt = 0; nt < 4; nt++)
                mma_f32acc(acc[mt][nt], a[mt], b[nt]);
    }

    #pragma unroll
    for (int mt = 0; mt < 4; mt++) {
        int row0 = rt * TILE + wr * 64 + mt * 16 + (lane >> 2);
        float tAcc[2];
        #pragma unroll
        for (int h = 0; h < 2; h++) {
            int row    = row0 + h * 8;
            float S    = g_neg_sum[row];
            float logS = __logf(S);
            float invS = 1.0f / S;
            float sum  = 0.0f;
            #pragma unroll
            for (int nt = 0; nt < 4; nt++) {
                int colBase = ct * TILE + wc * 32 + nt * 8 + ((lane & 3) << 1);
                #pragma unroll
                for (int cc = 0; cc < 2; cc++) {
                    int col = colBase + cc;
                    if (col != row) {
                        float a = acc[mt][nt][h * 2 + cc];
                        float l = fmaf(2.0f, a, -2.0f);
                        float e = fexp2(l * LOG2E);
                        float x = e * invS;
                        sum += l - logS - x + 0.5f * x * x;
                    }
                }
            }
            tAcc[h] = sum;
        }
        #pragma unroll
        for (int h = 0; h < 2; h++) {
            float v = tAcc[h];
            v += __shfl_xor_sync(0xFFFFFFFFu, v, 1);
            v += __shfl_xor_sync(0xFFFFFFFFu, v, 2);
            if ((lane & 3) == 0) {
                int row = row0 + h * 8;
                atomicAdd(&g_row_loss[row], v);
            }
        }
    }
}

// ---------------------------------------------------------------------------
// K4: final reduction
// ---------------------------------------------------------------------------
__global__ void k_final(const int* __restrict__ labels, float* __restrict__ out) {
    __shared__ int   lab[TT];
    __shared__ float invpc[TT];
    __shared__ float ws[8];
    int tid = threadIdx.x;
    if (tid < TT) lab[tid] = labels[tid];
    __syncthreads();
    if (tid < TT) {
        int ns = 0;
        #pragma unroll
        for (int j = 0; j < TT; j++) ns += (lab[j] == lab[tid]);
        invpc[tid] = 1.0f / (float)(ns * VV - 1);
    }
    __syncthreads();

    float s = 0.0f;
    for (int i = tid; i < TV; i += 256) s += g_row_loss[i] * invpc[i >> 8];
    #pragma unroll
    for (int o = 16; o; o >>= 1) s += __shfl_xor_sync(0xFFFFFFFFu, s, o);
    if ((tid & 31) == 0) ws[tid >> 5] = s;
    __syncthreads();
    if (tid == 0) {
        float t = 0.0f;
        #pragma unroll
        for (int w = 0; w < 8; w++) t += ws[w];
        out[0] = -(t / (float)TV);
    }
}

// ---------------------------------------------------------------------------
extern "C" void kernel_launch(void* const* d_in, const int* in_sizes, int n_in,
                              void* d_out, int out_size) {
    const float* features    = (const float*)d_in[0];
    const int*   batch_inds  = (const int*)d_in[1];
    const void*  sample_inds = (const void*)d_in[2];
    const int*   labels      = (const int*)d_in[3];
    float*       out         = (float*)d_out;

    static bool attr_set = false;
    if (!attr_set) {
        cudaFuncSetAttribute(k_negpair, cudaFuncAttributeMaxDynamicSharedMemorySize, SMEM_BYTES_NEG);
        cudaFuncSetAttribute(k_pos,     cudaFuncAttributeMaxDynamicSharedMemorySize, SMEM_BYTES_POS);
        attr_set = true;
    }

    k_detect<<<1, 256>>>((const unsigned int*)sample_inds);
    k_zero<<<(TV + 255) / 256, 256>>>();
    k_gather<<<TV, 256>>>(features, batch_inds, sample_inds);
    k_negpair<<<dim3(NTILES, NTILES), 256, SMEM_BYTES_NEG>>>(labels);
    k_pos<<<dim3(NTILES, NTILES), 256, SMEM_BYTES_POS>>>(labels);
    k_final<<<1, 256>>>(labels, out);
}